// round 9
// baseline (speedup 1.0000x reference)
#include <cuda_runtime.h>
#include <cuda_fp8.h>
#include <cstdint>

// ============================================================================
// Linear8bit on plain sm_103 (no 'a' target -> no tcgen05). Legacy FP8 QMMA:
//   mma.sync.aligned.m16n8k32.row.col.f32.e4m3.e4m3.f32   (real HW @ 1024
//   MACs/cyc/SM; int8 mma.sync is dp4a-emulated -- measured R4/R5).
//
// R9: R8 skeleton (occ 2, 3-stage cp.async, CTA 128x128, warps 4x2, warp tile
// 32x64) + issue-slot diet: all cp.async addressing hoisted out of the k-loop
// (incremental pointers, loop-invariant swizzled smem offsets, rotating stage
// bases) and kk0's LDSMs issued before the next-stage cp.async burst.
// ============================================================================

namespace l8 {

constexpr int Bn = 4, Mdim = 2048, Kdim = 4096, Ndim = 4096;
constexpr int ROWS = Bn * Mdim;          // 8192
constexpr int BM = 128, BN = 128, BK = 128;
constexpr int KITERS = Kdim / BK;        // 32
constexpr int STAGES = 3;
constexpr int NTHREADS = 256;

constexpr int A_BYTES = BM * BK;         // 16 KB
constexpr int B_BYTES = BN * BK;         // 16 KB
constexpr int STAGE_BYTES = A_BYTES + B_BYTES;          // 32 KB
constexpr int SMEM_TOTAL = STAGES * STAGE_BYTES;        // 96 KB

__device__ uint8_t g_xq8[(size_t)ROWS * Kdim];   // 33.5 MB (e4m3)
__device__ uint8_t g_w8[(size_t)Ndim * Kdim];    // 16.8 MB (e4m3)

// ---- fused pack: int32 -> e4m3, both tensors in one launch, 4 int4/thread --
constexpr int XQ_N4 = ROWS * Kdim / 4;
constexpr int W_N4  = Ndim * Kdim / 4;
constexpr int PACK_PER_THREAD = 4;
constexpr int PACK_TOTAL = XQ_N4 + W_N4;
constexpr int PACK_BLOCKS = (PACK_TOTAL / PACK_PER_THREAD + 255) / 256;

__device__ __forceinline__ uchar4 cvt4(int4 v) {
  uchar4 o;
  o.x = (uint8_t)__nv_cvt_float_to_fp8((float)v.x, __NV_SATFINITE, __NV_E4M3);
  o.y = (uint8_t)__nv_cvt_float_to_fp8((float)v.y, __NV_SATFINITE, __NV_E4M3);
  o.z = (uint8_t)__nv_cvt_float_to_fp8((float)v.z, __NV_SATFINITE, __NV_E4M3);
  o.w = (uint8_t)__nv_cvt_float_to_fp8((float)v.w, __NV_SATFINITE, __NV_E4M3);
  return o;
}

__global__ void pack_fp8_fused(const int4* __restrict__ xq,
                               const int4* __restrict__ w) {
  int i0 = (blockIdx.x * blockDim.x + threadIdx.x) * PACK_PER_THREAD;
  int4 v[PACK_PER_THREAD];
  const int4* src;
  uchar4* dst;
  int base;
  if (i0 < XQ_N4) {
    src = xq; dst = (uchar4*)g_xq8; base = i0;
  } else {
    src = w; dst = (uchar4*)g_w8; base = i0 - XQ_N4;
  }
#pragma unroll
  for (int j = 0; j < PACK_PER_THREAD; ++j) v[j] = src[base + j];
#pragma unroll
  for (int j = 0; j < PACK_PER_THREAD; ++j) dst[base + j] = cvt4(v[j]);
}

__device__ __forceinline__ uint32_t smem_u32(const void* p) {
  uint32_t a;
  asm("{ .reg .u64 t; cvta.to.shared.u64 t, %1; cvt.u32.u64 %0, t; }"
      : "=r"(a) : "l"(p));
  return a;
}
__device__ __forceinline__ uint32_t sw128(uint32_t o) {
  return o ^ ((o >> 3) & 0x70);
}
__device__ __forceinline__ void cp16(uint32_t s, const void* g) {
  asm volatile("cp.async.cg.shared.global [%0], [%1], 16;"
               :: "r"(s), "l"(g) : "memory");
}
__device__ __forceinline__ void cp_commit() {
  asm volatile("cp.async.commit_group;" ::: "memory");
}
__device__ __forceinline__ void cp_wait1() {
  asm volatile("cp.async.wait_group 1;" ::: "memory");
}
__device__ __forceinline__ void ldm_x4(uint32_t* r, uint32_t addr) {
  asm volatile(
      "ldmatrix.sync.aligned.m8n8.x4.shared.b16 {%0,%1,%2,%3}, [%4];"
      : "=r"(r[0]), "=r"(r[1]), "=r"(r[2]), "=r"(r[3]) : "r"(addr));
}
__device__ __forceinline__ void mma_e4m3(float* d, const uint32_t* a,
                                         uint32_t b0, uint32_t b1) {
  asm volatile(
      "mma.sync.aligned.m16n8k32.row.col.f32.e4m3.e4m3.f32 "
      "{%0,%1,%2,%3}, {%4,%5,%6,%7}, {%8,%9}, {%0,%1,%2,%3};"
      : "+f"(d[0]), "+f"(d[1]), "+f"(d[2]), "+f"(d[3])
      : "r"(a[0]), "r"(a[1]), "r"(a[2]), "r"(a[3]), "r"(b0), "r"(b1));
}

__global__ void __launch_bounds__(NTHREADS, 2)
linear8_kernel(const float* __restrict__ sx, const float* __restrict__ ws,
               const float* __restrict__ bias, float* __restrict__ out) {
  extern __shared__ char smem[];
  const uint32_t smem_base = smem_u32(smem);
  const int tid = threadIdx.x;
  const int lane = tid & 31;
  const int wid = tid >> 5;
  const int wr = wid >> 1;          // warp row 0..3 -> 32 M rows each
  const int wc = wid & 1;           // warp col 0..1 -> 64 N cols each

  const int mtile = blockIdx.x & (ROWS / BM - 1);  // 64 (fast-varying)
  const int ntile = blockIdx.x >> 6;               // 32

  // ---- loop-invariant cp.async addressing (computed ONCE) ----
  // thread loads rows {r0, r0+32, r0+64, r0+96}, 16B chunk c, of each tensor.
  const int lrow_ld = tid >> 3;      // 0..31
  const int lcol_ld = tid & 7;       // 0..7
  const uint8_t* ag = g_xq8 + (size_t)(mtile * BM + lrow_ld) * Kdim
                      + lcol_ld * 16;
  const uint8_t* bg = g_w8 + (size_t)(ntile * BN + lrow_ld) * Kdim
                      + lcol_ld * 16;
  // swizzled within-stage smem offset (row&7 invariant under +32 rows,
  // so +i*4096 deltas stay swizzle-correct)
  const uint32_t sm_off = sw128((uint32_t)(lrow_ld * BK + lcol_ld * 16));

  // one pipeline-stage load: A 16KB + B 16KB, one commit group
  auto load_stage = [&](uint32_t st, const uint8_t* a_p, const uint8_t* b_p) {
    const uint32_t as = st + sm_off;
    const uint32_t bs = st + A_BYTES + sm_off;
#pragma unroll
    for (int i = 0; i < 4; ++i)
      cp16(as + i * 4096, a_p + (size_t)i * 32 * Kdim);
#pragma unroll
    for (int i = 0; i < 4; ++i)
      cp16(bs + i * 4096, b_p + (size_t)i * 32 * Kdim);
    cp_commit();
  };

  // ---- LDSM addressing constants ----
  const int lrow = lane & 15;
  const int lc = lane >> 4;
  const int arow0 = wr * 32 + lrow;
  const int arow1 = arow0 + 16;
  const int brow0 = wc * 64 + lrow;

  float acc[2][8][4];
#pragma unroll
  for (int mi = 0; mi < 2; ++mi)
#pragma unroll
    for (int ni = 0; ni < 8; ++ni)
#pragma unroll
      for (int j = 0; j < 4; ++j) acc[mi][ni][j] = 0.f;

  // ---- prologue: stages 0,1 ----
  load_stage(smem_base, ag, bg);
  load_stage(smem_base + STAGE_BYTES, ag + BK, bg + BK);
  const uint8_t* ag_ld = ag + 2 * BK;
  const uint8_t* bg_ld = bg + 2 * BK;
  uint32_t ld_st = smem_base + 2 * STAGE_BYTES;  // next load stage base
  uint32_t cm_st = smem_base;                    // current compute stage base

  uint32_t afr[2][4], bfr[4][4];
  auto ldm6 = [&](uint32_t a_st, uint32_t b_st, int kk) {
    const uint32_t ch = (uint32_t)(kk * 2 + lc);
    ldm_x4(afr[0], a_st + (uint32_t)(arow0 * BK) +
                       ((ch ^ (uint32_t)(arow0 & 7)) << 4));
    ldm_x4(afr[1], a_st + (uint32_t)(arow1 * BK) +
                       ((ch ^ (uint32_t)(arow1 & 7)) << 4));
#pragma unroll
    for (int p = 0; p < 4; ++p) {
      const int brow = brow0 + p * 16;
      ldm_x4(bfr[p], b_st + (uint32_t)(brow * BK) +
                         ((ch ^ (uint32_t)(brow & 7)) << 4));
    }
  };
  auto mma16 = [&]() {
#pragma unroll
    for (int mi = 0; mi < 2; ++mi)
#pragma unroll
      for (int p = 0; p < 4; ++p) {
        mma_e4m3(acc[mi][2 * p + 0], afr[mi], bfr[p][0], bfr[p][2]);
        mma_e4m3(acc[mi][2 * p + 1], afr[mi], bfr[p][1], bfr[p][3]);
      }
  };

  for (int k = 0; k < KITERS; ++k) {
    cp_wait1();
    __syncthreads();

    const uint32_t a_st = cm_st;
    const uint32_t b_st = cm_st + A_BYTES;

    // kk=0 fragment loads first; next-stage cp.async burst hides in their
    // latency shadow.
    ldm6(a_st, b_st, 0);
    if (k + STAGES - 1 < KITERS) {
      load_stage(ld_st, ag_ld, bg_ld);
      ag_ld += BK;
      bg_ld += BK;
      ld_st += STAGE_BYTES;
      if (ld_st == smem_base + STAGES * STAGE_BYTES) ld_st = smem_base;
    } else {
      cp_commit();  // empty group keeps wait_group accounting uniform
    }
    mma16();
#pragma unroll
    for (int kk = 1; kk < 4; ++kk) {
      ldm6(a_st, b_st, kk);
      mma16();
    }

    cm_st += STAGE_BYTES;
    if (cm_st == smem_base + STAGES * STAGE_BYTES) cm_st = smem_base;
  }

  // ---- epilogue: fused dequant + bias, float2 stores ----
  const int qrow = lane >> 2;            // 0..7
  const int qcol = (lane & 3) * 2;       // 0,2,4,6
  const int gcol_base = ntile * BN + wc * 64 + qcol;
  const int grow_base = mtile * BM + wr * 32 + qrow;

#pragma unroll
  for (int mi = 0; mi < 2; ++mi) {
    const int r0 = grow_base + mi * 16;
    const int r1 = r0 + 8;
    const float sx0 = __ldg(sx + r0);
    const float sx1 = __ldg(sx + r1);
    float* o0 = out + (size_t)r0 * Ndim + gcol_base;
    float* o1 = out + (size_t)r1 * Ndim + gcol_base;
#pragma unroll
    for (int ni = 0; ni < 8; ++ni) {
      const int c = gcol_base + ni * 8;
      const float2 w2 = __ldg((const float2*)(ws + c));
      const float2 b2 = __ldg((const float2*)(bias + c));
      float2 v0, v1;
      v0.x = acc[mi][ni][0] * (sx0 * w2.x) + b2.x;
      v0.y = acc[mi][ni][1] * (sx0 * w2.y) + b2.y;
      v1.x = acc[mi][ni][2] * (sx1 * w2.x) + b2.x;
      v1.y = acc[mi][ni][3] * (sx1 * w2.y) + b2.y;
      *(float2*)(o0 + ni * 8) = v0;
      *(float2*)(o1 + ni * 8) = v1;
    }
  }
}

}  // namespace l8

extern "C" void kernel_launch(void* const* d_in, const int* in_sizes, int n_in,
                              void* d_out, int out_size) {
  (void)in_sizes; (void)n_in; (void)out_size;
  const int*   xq_i32 = (const int*)d_in[0];
  const float* sx     = (const float*)d_in[1];
  const int*   w_i32  = (const int*)d_in[2];
  const float* ws     = (const float*)d_in[3];
  const float* bia    = (const float*)d_in[4];
  float* out = (float*)d_out;

  l8::pack_fp8_fused<<<l8::PACK_BLOCKS, 256>>>((const int4*)xq_i32,
                                               (const int4*)w_i32);

  cudaFuncSetAttribute(l8::linear8_kernel,
                       cudaFuncAttributeMaxDynamicSharedMemorySize,
                       l8::SMEM_TOTAL);
  dim3 grid((l8::ROWS / l8::BM) * (l8::Ndim / l8::BN));  // 2048
  l8::linear8_kernel<<<grid, l8::NTHREADS, l8::SMEM_TOTAL>>>(
      sx, ws, bia, out);
}

// round 11
// speedup vs baseline: 1.0566x; 1.0566x over previous
#include <cuda_runtime.h>
#include <cuda_fp8.h>
#include <cstdint>

// ============================================================================
// Linear8bit on plain sm_103 (no 'a' target -> no tcgen05). Legacy FP8 QMMA:
//   mma.sync.aligned.m16n8k32.row.col.f32.e4m3.e4m3.f32  (real HW @ ~1024
//   MACs/cyc/SM; int8 mma.sync is dp4a-emulated -- measured R4/R5).
//
// R11 = R10 with the deadlock fixed: cp.async.mbarrier.arrive must be the
// .noinc variant when the init count equals the number of async arrivals
// (default variant nets pending to zero change -> barrier never completes).
// Per-stage mbarrier pipeline (full[s]: 256 noinc cp.async arrivals;
// empty[s]: 8 per-warp arrivals) replaces wait_group+__syncthreads so warps
// drift and LDSM bursts overlap MMA tails (crossbar/tensor decoupling).
// ============================================================================

namespace l8 {

constexpr int Bn = 4, Mdim = 2048, Kdim = 4096, Ndim = 4096;
constexpr int ROWS = Bn * Mdim;          // 8192
constexpr int BM = 128, BN = 128, BK = 128;
constexpr int KITERS = Kdim / BK;        // 32
constexpr int STAGES = 3;
constexpr int NTHREADS = 256;
constexpr int NWARPS = NTHREADS / 32;    // 8

constexpr int A_BYTES = BM * BK;         // 16 KB
constexpr int B_BYTES = BN * BK;         // 16 KB
constexpr int STAGE_BYTES = A_BYTES + B_BYTES;          // 32 KB
constexpr int SMEM_TOTAL = STAGES * STAGE_BYTES;        // 96 KB

__device__ uint8_t g_xq8[(size_t)ROWS * Kdim];   // 33.5 MB (e4m3)
__device__ uint8_t g_w8[(size_t)Ndim * Kdim];    // 16.8 MB (e4m3)

// ---- fused pack: int32 -> e4m3, both tensors in one launch, 4 int4/thread --
constexpr int XQ_N4 = ROWS * Kdim / 4;
constexpr int W_N4  = Ndim * Kdim / 4;
constexpr int PACK_PER_THREAD = 4;
constexpr int PACK_TOTAL = XQ_N4 + W_N4;
constexpr int PACK_BLOCKS = (PACK_TOTAL / PACK_PER_THREAD + 255) / 256;

__device__ __forceinline__ uchar4 cvt4(int4 v) {
  uchar4 o;
  o.x = (uint8_t)__nv_cvt_float_to_fp8((float)v.x, __NV_SATFINITE, __NV_E4M3);
  o.y = (uint8_t)__nv_cvt_float_to_fp8((float)v.y, __NV_SATFINITE, __NV_E4M3);
  o.z = (uint8_t)__nv_cvt_float_to_fp8((float)v.z, __NV_SATFINITE, __NV_E4M3);
  o.w = (uint8_t)__nv_cvt_float_to_fp8((float)v.w, __NV_SATFINITE, __NV_E4M3);
  return o;
}

__global__ void pack_fp8_fused(const int4* __restrict__ xq,
                               const int4* __restrict__ w) {
  int i0 = (blockIdx.x * blockDim.x + threadIdx.x) * PACK_PER_THREAD;
  int4 v[PACK_PER_THREAD];
  const int4* src;
  uchar4* dst;
  int base;
  if (i0 < XQ_N4) {
    src = xq; dst = (uchar4*)g_xq8; base = i0;
  } else {
    src = w; dst = (uchar4*)g_w8; base = i0 - XQ_N4;
  }
#pragma unroll
  for (int j = 0; j < PACK_PER_THREAD; ++j) v[j] = src[base + j];
#pragma unroll
  for (int j = 0; j < PACK_PER_THREAD; ++j) dst[base + j] = cvt4(v[j]);
}

__device__ __forceinline__ uint32_t smem_u32(const void* p) {
  uint32_t a;
  asm("{ .reg .u64 t; cvta.to.shared.u64 t, %1; cvt.u32.u64 %0, t; }"
      : "=r"(a) : "l"(p));
  return a;
}
__device__ __forceinline__ uint32_t sw128(uint32_t o) {
  return o ^ ((o >> 3) & 0x70);
}
__device__ __forceinline__ void cp16(uint32_t s, const void* g) {
  asm volatile("cp.async.cg.shared.global [%0], [%1], 16;"
               :: "r"(s), "l"(g) : "memory");
}
__device__ __forceinline__ void mbar_init(uint32_t a, uint32_t cnt) {
  asm volatile("mbarrier.init.shared.b64 [%0], %1;"
               :: "r"(a), "r"(cnt) : "memory");
}
__device__ __forceinline__ void mbar_arrive(uint32_t a) {
  asm volatile("mbarrier.arrive.shared.b64 _, [%0];" :: "r"(a) : "memory");
}
__device__ __forceinline__ void cp_arrive_noinc(uint32_t a) {
  asm volatile("cp.async.mbarrier.arrive.noinc.shared.b64 [%0];"
               :: "r"(a) : "memory");
}
__device__ __forceinline__ void mbar_wait(uint32_t a, uint32_t parity) {
  asm volatile(
      "{\n\t"
      ".reg .pred P;\n\t"
      "LW_%=:\n\t"
      "mbarrier.try_wait.parity.shared.b64 P, [%0], %1;\n\t"
      "@!P bra LW_%=;\n\t"
      "}"
      :: "r"(a), "r"(parity) : "memory");
}
__device__ __forceinline__ void ldm_x4(uint32_t* r, uint32_t addr) {
  asm volatile(
      "ldmatrix.sync.aligned.m8n8.x4.shared.b16 {%0,%1,%2,%3}, [%4];"
      : "=r"(r[0]), "=r"(r[1]), "=r"(r[2]), "=r"(r[3]) : "r"(addr));
}
__device__ __forceinline__ void mma_e4m3(float* d, const uint32_t* a,
                                         uint32_t b0, uint32_t b1) {
  asm volatile(
      "mma.sync.aligned.m16n8k32.row.col.f32.e4m3.e4m3.f32 "
      "{%0,%1,%2,%3}, {%4,%5,%6,%7}, {%8,%9}, {%0,%1,%2,%3};"
      : "+f"(d[0]), "+f"(d[1]), "+f"(d[2]), "+f"(d[3])
      : "r"(a[0]), "r"(a[1]), "r"(a[2]), "r"(a[3]), "r"(b0), "r"(b1));
}

__global__ void __launch_bounds__(NTHREADS, 2)
linear8_kernel(const float* __restrict__ sx, const float* __restrict__ ws,
               const float* __restrict__ bias, float* __restrict__ out) {
  extern __shared__ char smem[];
  __shared__ __align__(8) unsigned long long mb[2 * STAGES];
  const uint32_t smem_base = smem_u32(smem);
  const uint32_t mb_base = smem_u32(mb);  // full[s]=mb_base+8s, empty=+24+8s
  const int tid = threadIdx.x;
  const int lane = tid & 31;
  const int wid = tid >> 5;
  const int wr = wid >> 1;          // warp row 0..3 -> 32 M rows each
  const int wc = wid & 1;           // warp col 0..1 -> 64 N cols each

  const int mtile = blockIdx.x & (ROWS / BM - 1);  // 64 (fast-varying)
  const int ntile = blockIdx.x >> 6;               // 32

  const uint8_t* a_base = g_xq8 + (size_t)mtile * BM * Kdim;
  const uint8_t* b_base = g_w8 + (size_t)ntile * BN * Kdim;

  if (tid == 0) {
#pragma unroll
    for (int s = 0; s < STAGES; ++s) {
      mbar_init(mb_base + 8 * s, NTHREADS);      // full: noinc async arrivals
      mbar_init(mb_base + 24 + 8 * s, NWARPS);   // empty: per-warp
    }
  }
  __syncthreads();

  // one pipeline-stage load + noinc cp.async arrive on full[s]
  auto load_stage = [&](int s, int kiter) {
    const uint8_t* ag = a_base + (size_t)kiter * BK;
    const uint8_t* bg = b_base + (size_t)kiter * BK;
    const uint32_t as = smem_base + s * STAGE_BYTES;
    const uint32_t bs = as + A_BYTES;
#pragma unroll
    for (int i = 0; i < 4; ++i) {
      int idx = tid + i * NTHREADS;
      int row = idx >> 3, c = idx & 7;
      cp16(as + sw128((uint32_t)(row * BK + c * 16)),
           ag + (size_t)row * Kdim + c * 16);
    }
#pragma unroll
    for (int i = 0; i < 4; ++i) {
      int idx = tid + i * NTHREADS;
      int row = idx >> 3, c = idx & 7;
      cp16(bs + sw128((uint32_t)(row * BK + c * 16)),
           bg + (size_t)row * Kdim + c * 16);
    }
    cp_arrive_noinc(mb_base + 8 * s);
  };

  const int lrow = lane & 15;
  const int lc = lane >> 4;
  const int arow0 = wr * 32 + lrow;
  const int arow1 = arow0 + 16;
  const int brow0 = wc * 64 + lrow;

  float acc[2][8][4];
#pragma unroll
  for (int mi = 0; mi < 2; ++mi)
#pragma unroll
    for (int ni = 0; ni < 8; ++ni)
#pragma unroll
      for (int j = 0; j < 4; ++j) acc[mi][ni][j] = 0.f;

  // ---- prologue: fill stages 0,1 ----
  load_stage(0, 0);
  load_stage(1, 1);

  uint32_t afr[2][4], bfr[4][4];
  auto ldm6 = [&](uint32_t a_st, uint32_t b_st, int kk) {
    const uint32_t ch = (uint32_t)(kk * 2 + lc);
    ldm_x4(afr[0], a_st + (uint32_t)(arow0 * BK) +
                       ((ch ^ (uint32_t)(arow0 & 7)) << 4));
    ldm_x4(afr[1], a_st + (uint32_t)(arow1 * BK) +
                       ((ch ^ (uint32_t)(arow1 & 7)) << 4));
#pragma unroll
    for (int p = 0; p < 4; ++p) {
      const int brow = brow0 + p * 16;
      ldm_x4(bfr[p], b_st + (uint32_t)(brow * BK) +
                         ((ch ^ (uint32_t)(brow & 7)) << 4));
    }
  };
  auto mma16 = [&]() {
#pragma unroll
    for (int mi = 0; mi < 2; ++mi)
#pragma unroll
      for (int p = 0; p < 4; ++p) {
        mma_e4m3(acc[mi][2 * p + 0], afr[mi], bfr[p][0], bfr[p][2]);
        mma_e4m3(acc[mi][2 * p + 1], afr[mi], bfr[p][1], bfr[p][3]);
      }
  };

  for (int k = 0; k < KITERS; ++k) {
    const int s = k % STAGES;
    const int u = k / STAGES;
    mbar_wait(mb_base + 8 * s, (uint32_t)(u & 1));  // stage data ready

    const uint32_t a_st = smem_base + s * STAGE_BYTES;
    const uint32_t b_st = a_st + A_BYTES;

    ldm6(a_st, b_st, 0);
    mma16();

    const int kn = k + STAGES - 1;
    if (kn < KITERS) {
      const int sn = kn % STAGES;
      const int un = kn / STAGES;
      if (un > 0)  // stage reuse: wait consumers of previous occupant
        mbar_wait(mb_base + 24 + 8 * sn, (uint32_t)((un - 1) & 1));
      load_stage(sn, kn);
    }

#pragma unroll
    for (int kk = 1; kk < 4; ++kk) {
      ldm6(a_st, b_st, kk);
      mma16();
    }

    if (lane == 0) mbar_arrive(mb_base + 24 + 8 * s);  // warp done with stage
  }

  // ---- epilogue: fused dequant + bias, float2 stores ----
  const int qrow = lane >> 2;            // 0..7
  const int qcol = (lane & 3) * 2;       // 0,2,4,6
  const int gcol_base = ntile * BN + wc * 64 + qcol;
  const int grow_base = mtile * BM + wr * 32 + qrow;

#pragma unroll
  for (int mi = 0; mi < 2; ++mi) {
    const int r0 = grow_base + mi * 16;
    const int r1 = r0 + 8;
    const float sx0 = __ldg(sx + r0);
    const float sx1 = __ldg(sx + r1);
    float* o0 = out + (size_t)r0 * Ndim + gcol_base;
    float* o1 = out + (size_t)r1 * Ndim + gcol_base;
#pragma unroll
    for (int ni = 0; ni < 8; ++ni) {
      const int c = gcol_base + ni * 8;
      const float2 w2 = __ldg((const float2*)(ws + c));
      const float2 b2 = __ldg((const float2*)(bias + c));
      float2 v0, v1;
      v0.x = acc[mi][ni][0] * (sx0 * w2.x) + b2.x;
      v0.y = acc[mi][ni][1] * (sx0 * w2.y) + b2.y;
      v1.x = acc[mi][ni][2] * (sx1 * w2.x) + b2.x;
      v1.y = acc[mi][ni][3] * (sx1 * w2.y) + b2.y;
      *(float2*)(o0 + ni * 8) = v0;
      *(float2*)(o1 + ni * 8) = v1;
    }
  }
}

}  // namespace l8

extern "C" void kernel_launch(void* const* d_in, const int* in_sizes, int n_in,
                              void* d_out, int out_size) {
  (void)in_sizes; (void)n_in; (void)out_size;
  const int*   xq_i32 = (const int*)d_in[0];
  const float* sx     = (const float*)d_in[1];
  const int*   w_i32  = (const int*)d_in[2];
  const float* ws     = (const float*)d_in[3];
  const float* bia    = (const float*)d_in[4];
  float* out = (float*)d_out;

  l8::pack_fp8_fused<<<l8::PACK_BLOCKS, 256>>>((const int4*)xq_i32,
                                               (const int4*)w_i32);

  cudaFuncSetAttribute(l8::linear8_kernel,
                       cudaFuncAttributeMaxDynamicSharedMemorySize,
                       l8::SMEM_TOTAL);
  dim3 grid((l8::ROWS / l8::BM) * (l8::Ndim / l8::BN));  // 2048
  l8::linear8_kernel<<<grid, l8::NTHREADS, l8::SMEM_TOTAL>>>(
      sx, ws, bia, out);
}